// round 1
// baseline (speedup 1.0000x reference)
#include <cuda_runtime.h>

#define HEADS 8
#define CH 32
#define NMAX 50000
#define EMAX 400000

// Scratch (device globals — no runtime allocation allowed)
__device__ float g_kn[NMAX * HEADS * CH];   // RMSNorm'd K
__device__ int   g_rowptr[NMAX + 1];        // segment starts per destination

__device__ __forceinline__ float warp_sum(float v) {
#pragma unroll
    for (int o = 16; o; o >>= 1) v += __shfl_xor_sync(0xffffffffu, v, o);
    return v;
}

// ---------------------------------------------------------------------------
// Kernel 1: kn = RMSNorm(k) * w_k  — one warp per (node, head) row of 32
// ---------------------------------------------------------------------------
__global__ void kn_kernel(const float* __restrict__ k,
                          const float* __restrict__ w,
                          int nrows) {
    int row  = blockIdx.x * (blockDim.x >> 5) + (threadIdx.x >> 5);
    int lane = threadIdx.x & 31;
    if (row >= nrows) return;
    float x  = k[row * CH + lane];
    float ss = warp_sum(x * x);
    float r  = rsqrtf(ss * (1.0f / CH) + 1e-6f);
    g_kn[row * CH + lane] = x * r * w[lane];
}

// ---------------------------------------------------------------------------
// Kernel 2: row_ptr[d] = lower_bound(edge_dst, d)  (edge_dst is sorted)
// ---------------------------------------------------------------------------
__global__ void rowptr_kernel(const int* __restrict__ dst, int E, int N) {
    int d = blockIdx.x * blockDim.x + threadIdx.x;
    if (d > N) return;
    int lo = 0, hi = E;
    while (lo < hi) {
        int mid = (lo + hi) >> 1;
        if (dst[mid] < d) lo = mid + 1; else hi = mid;
    }
    g_rowptr[d] = lo;
}

// ---------------------------------------------------------------------------
// Kernel 3: fused gather + dot + online segment softmax + weighted accumulate
//   block  = destination node (reads its contiguous edge range)
//   warp   = head  (8 warps = 8 heads, 256 threads/block)
//   lane   = channel (32 lanes = C=32) -> every global load is a 128B line
// ---------------------------------------------------------------------------
__global__ void attn_kernel(const float* __restrict__ q,
                            const float* __restrict__ v,
                            const float* __restrict__ e,
                            const float* __restrict__ wq,
                            const int*   __restrict__ src,
                            float* __restrict__ out) {
    const int d    = blockIdx.x;
    const int h    = threadIdx.x >> 5;
    const int lane = threadIdx.x & 31;

    const int start = g_rowptr[d];
    const int end   = g_rowptr[d + 1];

    // Inline RMSNorm of the query row (once per (dst, head))
    float qx = q[(d * HEADS + h) * CH + lane];
    float ss = warp_sum(qx * qx);
    float qn = qx * rsqrtf(ss * (1.0f / CH) + 1e-6f) * wq[lane];

    const float scale = 0.1767766952966369f;  // 1/sqrt(32)

    float m = -1e30f, l = 0.0f, acc = 0.0f;

    for (int eid = start; eid < end; eid++) {
        int   s  = src[eid];
        float ec = e[(eid * HEADS + h) * CH + lane];
        float kc = g_kn[(s * HEADS + h) * CH + lane];
        float vc = v[(s * HEADS + h) * CH + lane];

        float sdot = warp_sum(qn * (kc + ec)) * scale;   // warp-uniform

        float mnew = fmaxf(m, sdot);
        float corr = __expf(m - mnew);       // 0 on first iter (m=-1e30)
        float p    = __expf(sdot - mnew);
        l   = l * corr + p;
        acc = acc * corr + p * (vc + ec);
        m   = mnew;
    }

    out[(d * HEADS + h) * CH + lane] = (l > 0.0f) ? acc / l : 0.0f;
}

// ---------------------------------------------------------------------------
// Launch
// ---------------------------------------------------------------------------
extern "C" void kernel_launch(void* const* d_in, const int* in_sizes, int n_in,
                              void* d_out, int out_size) {
    const float* q    = (const float*)d_in[0];
    const float* k    = (const float*)d_in[1];
    const float* v    = (const float*)d_in[2];
    const float* e    = (const float*)d_in[3];
    const float* wq   = (const float*)d_in[4];
    const float* wk   = (const float*)d_in[5];
    const int*   esrc = (const int*)d_in[6];
    const int*   edst = (const int*)d_in[7];

    const int N = in_sizes[0] / (HEADS * CH);
    const int E = in_sizes[6];
    const int nrows = N * HEADS;

    kn_kernel<<<(nrows + 7) / 8, 256>>>(k, wk, nrows);
    rowptr_kernel<<<(N + 256) / 256, 256>>>(edst, E, N);
    attn_kernel<<<N, 256>>>(q, v, e, wq, esrc, (float*)d_out);
}

// round 3
// speedup vs baseline: 1.1940x; 1.1940x over previous
#include <cuda_runtime.h>

#define HEADS 8
#define CH 32
#define NMAX 50000
#define EMAX 400000

__device__ float g_kn[NMAX * HEADS * CH];   // RMSNorm'd K
__device__ int   g_rowptr[NMAX + 1];        // per-destination segment starts

__device__ __forceinline__ float warp_sum(float v) {
#pragma unroll
    for (int o = 16; o; o >>= 1) v += __shfl_xor_sync(0xffffffffu, v, o);
    return v;
}

// ---------------------------------------------------------------------------
// Kernel 1: kn = RMSNorm(k) * w_k — 4 rows per warp (4 independent chains)
// ---------------------------------------------------------------------------
__global__ void kn_kernel(const float* __restrict__ k,
                          const float* __restrict__ w,
                          int nrows) {
    int warp = blockIdx.x * (blockDim.x >> 5) + (threadIdx.x >> 5);
    int lane = threadIdx.x & 31;
    int r0 = warp * 4;
    if (r0 >= nrows) return;
    float wl = w[lane];

    float x0 = k[(r0 + 0) * CH + lane];
    float x1 = (r0 + 1 < nrows) ? k[(r0 + 1) * CH + lane] : 0.0f;
    float x2 = (r0 + 2 < nrows) ? k[(r0 + 2) * CH + lane] : 0.0f;
    float x3 = (r0 + 3 < nrows) ? k[(r0 + 3) * CH + lane] : 0.0f;

    float s0 = x0 * x0, s1 = x1 * x1, s2 = x2 * x2, s3 = x3 * x3;
#pragma unroll
    for (int o = 16; o; o >>= 1) {
        s0 += __shfl_xor_sync(0xffffffffu, s0, o);
        s1 += __shfl_xor_sync(0xffffffffu, s1, o);
        s2 += __shfl_xor_sync(0xffffffffu, s2, o);
        s3 += __shfl_xor_sync(0xffffffffu, s3, o);
    }
    const float inv = 1.0f / CH;
    g_kn[(r0 + 0) * CH + lane] = x0 * rsqrtf(s0 * inv + 1e-6f) * wl;
    if (r0 + 1 < nrows) g_kn[(r0 + 1) * CH + lane] = x1 * rsqrtf(s1 * inv + 1e-6f) * wl;
    if (r0 + 2 < nrows) g_kn[(r0 + 2) * CH + lane] = x2 * rsqrtf(s2 * inv + 1e-6f) * wl;
    if (r0 + 3 < nrows) g_kn[(r0 + 3) * CH + lane] = x3 * rsqrtf(s3 * inv + 1e-6f) * wl;
}

// ---------------------------------------------------------------------------
// Kernel 2: row_ptr[d] = lower_bound(edge_dst, d)
// ---------------------------------------------------------------------------
__global__ void rowptr_kernel(const int* __restrict__ dst, int E, int N) {
    int d = blockIdx.x * blockDim.x + threadIdx.x;
    if (d > N) return;
    int lo = 0, hi = E;
    while (lo < hi) {
        int mid = (lo + hi) >> 1;
        if (dst[mid] < d) lo = mid + 1; else hi = mid;
    }
    g_rowptr[d] = lo;
}

// ---------------------------------------------------------------------------
// Kernel 3: fused gather + dot + online segment softmax, 4-edge pipeline
//   block = dst, warp = head, lane = channel
//   e (streamed once, 410MB) loaded via __ldcs so kn/v keep L2 residency
// ---------------------------------------------------------------------------
__global__ void attn_kernel(const float* __restrict__ q,
                            const float* __restrict__ v,
                            const float* __restrict__ e,
                            const float* __restrict__ wq,
                            const int*   __restrict__ src,
                            float* __restrict__ out) {
    const int d    = blockIdx.x;
    const int h    = threadIdx.x >> 5;
    const int lane = threadIdx.x & 31;

    const int start = g_rowptr[d];
    const int end   = g_rowptr[d + 1];

    // inline RMSNorm of q row
    float qx = q[(d * HEADS + h) * CH + lane];
    float ss = warp_sum(qx * qx);
    float qn = qx * rsqrtf(ss * (1.0f / CH) + 1e-6f) * wq[lane];

    const float scale = 0.1767766952966369f;  // 1/sqrt(32)
    const int hoff = h * CH + lane;

    float m = -1e30f, l = 0.0f, acc = 0.0f;

    int eid = start;
    for (; eid + 4 <= end; eid += 4) {
        // 1) all indices first (independent LDGs)
        int s0 = src[eid + 0];
        int s1 = src[eid + 1];
        int s2 = src[eid + 2];
        int s3 = src[eid + 3];

        // 2) streamed e rows (independent of s)
        float e0 = __ldcs(&e[(eid + 0) * HEADS * CH + hoff]);
        float e1 = __ldcs(&e[(eid + 1) * HEADS * CH + hoff]);
        float e2 = __ldcs(&e[(eid + 2) * HEADS * CH + hoff]);
        float e3 = __ldcs(&e[(eid + 3) * HEADS * CH + hoff]);

        // 3) gathers (depend only on s)
        float k0 = g_kn[s0 * HEADS * CH + hoff];
        float k1 = g_kn[s1 * HEADS * CH + hoff];
        float k2 = g_kn[s2 * HEADS * CH + hoff];
        float k3 = g_kn[s3 * HEADS * CH + hoff];
        float v0 = v[s0 * HEADS * CH + hoff];
        float v1 = v[s1 * HEADS * CH + hoff];
        float v2 = v[s2 * HEADS * CH + hoff];
        float v3 = v[s3 * HEADS * CH + hoff];

        // 4) four interleaved butterfly reductions (pipelined SHFLs)
        float d0 = qn * (k0 + e0);
        float d1 = qn * (k1 + e1);
        float d2 = qn * (k2 + e2);
        float d3 = qn * (k3 + e3);
#pragma unroll
        for (int o = 16; o; o >>= 1) {
            d0 += __shfl_xor_sync(0xffffffffu, d0, o);
            d1 += __shfl_xor_sync(0xffffffffu, d1, o);
            d2 += __shfl_xor_sync(0xffffffffu, d2, o);
            d3 += __shfl_xor_sync(0xffffffffu, d3, o);
        }
        d0 *= scale; d1 *= scale; d2 *= scale; d3 *= scale;

        // 5) online softmax update (scalar, cheap)
        float mn, corr, p;
        mn = fmaxf(m, d0); corr = __expf(m - mn); p = __expf(d0 - mn);
        l = l * corr + p; acc = acc * corr + p * (v0 + e0); m = mn;
        mn = fmaxf(m, d1); corr = __expf(m - mn); p = __expf(d1 - mn);
        l = l * corr + p; acc = acc * corr + p * (v1 + e1); m = mn;
        mn = fmaxf(m, d2); corr = __expf(m - mn); p = __expf(d2 - mn);
        l = l * corr + p; acc = acc * corr + p * (v2 + e2); m = mn;
        mn = fmaxf(m, d3); corr = __expf(m - mn); p = __expf(d3 - mn);
        l = l * corr + p; acc = acc * corr + p * (v3 + e3); m = mn;
    }

    for (; eid < end; eid++) {
        int   s  = src[eid];
        float ec = __ldcs(&e[eid * HEADS * CH + hoff]);
        float kc = g_kn[s * HEADS * CH + hoff];
        float vc = v[s * HEADS * CH + hoff];
        float sdot = warp_sum(qn * (kc + ec)) * scale;
        float mn   = fmaxf(m, sdot);
        float corr = __expf(m - mn);
        float p    = __expf(sdot - mn);
        l   = l * corr + p;
        acc = acc * corr + p * (vc + ec);
        m   = mn;
    }

    out[(d * HEADS + h) * CH + lane] = (l > 0.0f) ? acc / l : 0.0f;
}

// ---------------------------------------------------------------------------
extern "C" void kernel_launch(void* const* d_in, const int* in_sizes, int n_in,
                              void* d_out, int out_size) {
    const float* q    = (const float*)d_in[0];
    const float* k    = (const float*)d_in[1];
    const float* v    = (const float*)d_in[2];
    const float* e    = (const float*)d_in[3];
    const float* wq   = (const float*)d_in[4];
    const float* wk   = (const float*)d_in[5];
    const int*   esrc = (const int*)d_in[6];
    const int*   edst = (const int*)d_in[7];

    const int N = in_sizes[0] / (HEADS * CH);
    const int E = in_sizes[6];
    const int nrows = N * HEADS;

    int kn_warps  = (nrows + 3) / 4;
    int kn_blocks = (kn_warps + 7) / 8;
    kn_kernel<<<kn_blocks, 256>>>(k, wk, nrows);
    rowptr_kernel<<<(N + 256) / 256, 256>>>(edst, E, N);
    attn_kernel<<<N, 256>>>(q, v, e, wq, esrc, (float*)d_out);
}